// round 1
// baseline (speedup 1.0000x reference)
#include <cuda_runtime.h>
#include <cstdint>

#define NN 96
#define DD 64

// Scratch (allocation-free rule): device globals, recomputed deterministically every launch.
__device__ float g_X0[NN * DD];                       // z @ W1[:64]
__device__ unsigned g_mask[NN * 3];                   // adjacency bitmask rows
__device__ __align__(16) unsigned char g_nbr[NN * NN]; // sorted neighbor lists

__global__ void setup_x0_kernel(const float* __restrict__ z, const float* __restrict__ W1) {
    int row = blockIdx.x, c = threadIdx.x;   // 96 blocks x 64 threads
    __shared__ float zr[DD];
    zr[c] = z[row * DD + c];
    __syncthreads();
    float acc = 0.f;
#pragma unroll
    for (int k = 0; k < DD; k++) acc += zr[k] * W1[k * DD + c];
    g_X0[row * DD + c] = acc;
}

__global__ void setup_adj_kernel(const float* __restrict__ adj) {
    int row = blockIdx.x;                    // 96 blocks x 96 threads
    int t = threadIdx.x;
    __shared__ unsigned char flag[NN];
    flag[t] = (adj[row * NN + t] != 0.0f) ? 1 : 0;
    __syncthreads();
    unsigned bal = __ballot_sync(0xffffffffu, flag[t] != 0);
    if ((t & 31) == 0) g_mask[row * 3 + (t >> 5)] = bal;
    if (t == 0) {
        int c = 0;
        for (int b = 0; b < NN; b++)
            if (flag[b]) g_nbr[row * NN + c++] = (unsigned char)b;
        for (; c < NN; c++) g_nbr[row * NN + c] = 0;
    }
}

// bits [0, n) of 32-bit word w
__device__ __forceinline__ unsigned wmask(int n, int w) {
    int m = n - (w << 5);
    if (m <= 0) return 0u;
    if (m >= 32) return 0xffffffffu;
    return (1u << m) - 1u;
}

__global__ void __launch_bounds__(128) pair_kernel(const float* __restrict__ W1,
                                                   const float* __restrict__ W2,
                                                   float* __restrict__ out) {
    __shared__ float sY[NN * DD];   // deg^-1/2 - scaled, perturbed feature rows
    __shared__ float sS[NN];        // deg^-1/2
    __shared__ float sG[NN];        // s_m * (h1_m . W2)
    __shared__ int sCnt[NN];        // # neighbors below limit (list prefix length)
    __shared__ unsigned sMask[NN * 3];
    __shared__ __align__(16) unsigned char sNbr[NN * NN];
    __shared__ float sW2[DD];

    int p = blockIdx.x;
    int i = p / NN, j = p % NN;
    int U = i > j ? i : j;
    int L = i + j - U;
    int tid = threadIdx.x;
    int lane = tid & 31, warp = tid >> 5;

    for (int t = tid; t < NN * 3; t += 128) sMask[t] = g_mask[t];
    for (int t = tid; t < (NN * NN) / 4; t += 128)
        ((uint32_t*)sNbr)[t] = ((const uint32_t*)g_nbr)[t];
    if (tid < DD) sW2[tid] = W2[tid];
    __syncthreads();

    // degrees / scales for nodes 0..U
    if (tid <= U) {
        int k = tid;
        int lim = (k == U) ? L : U;   // node U only links to neighbors < L
        unsigned m0 = sMask[k * 3 + 0] & wmask(lim, 0);
        unsigned m1 = sMask[k * 3 + 1] & wmask(lim, 1);
        unsigned m2 = sMask[k * 3 + 2] & wmask(lim, 2);
        int cnt = __popc(m0) + __popc(m1) + __popc(m2);
        int deg = 1 + cnt;   // self loop
        if (k < L) deg += (sMask[U * 3 + (k >> 5)] >> (k & 31)) & 1;  // edge to U
        sS[k] = rsqrtf((float)deg);
        sCnt[k] = cnt;
    }
    __syncthreads();

    // load Y rows 0..U: X0 + onehot perturbations, pre-scaled by s_row
    int n4 = (U + 1) * (DD / 4);
    const float4* x04 = (const float4*)g_X0;
    for (int t = tid; t < n4; t += 128) {
        int row = t >> 4;
        int cb = (t & 15) * 4;
        float4 v = x04[t];
        if (row == i) {
            v.x += W1[64 * DD + cb + 0]; v.y += W1[64 * DD + cb + 1];
            v.z += W1[64 * DD + cb + 2]; v.w += W1[64 * DD + cb + 3];
        }
        if (row == j) {
            v.x += W1[65 * DD + cb + 0]; v.y += W1[65 * DD + cb + 1];
            v.z += W1[65 * DD + cb + 2]; v.w += W1[65 * DD + cb + 3];
        }
        float s = sS[row];
        v.x *= s; v.y *= s; v.z *= s; v.w *= s;
        ((float4*)sY)[t] = v;
    }
    __syncthreads();

    // h1 = relu(conv(Y)) ; g = s_m * (h1 . W2). One node per warp iteration.
    const float2* Y2 = (const float2*)sY;
    for (int m = warp; m <= U; m += 4) {
        float sm = sS[m];
        float2 acc = Y2[m * 32 + lane];              // self term (already s_m-scaled)
        int cnt = sCnt[m];
        const unsigned char* lst = &sNbr[m * NN];
        int q = 0;
        while (q < cnt) {
            unsigned pk = *(const unsigned*)(lst + q);   // q is multiple of 4, base 16B-aligned
            int rem = cnt - q;
#pragma unroll
            for (int e = 0; e < 4; e++) {
                if (e < rem) {
                    int b = (pk >> (8 * e)) & 255;
                    float2 yb = Y2[b * 32 + lane];
                    acc.x += yb.x; acc.y += yb.y;
                }
            }
            q += 4;
        }
        if (m < L && ((sMask[U * 3 + (m >> 5)] >> (m & 31)) & 1)) {
            float2 yu = Y2[U * 32 + lane];
            acc.x += yu.x; acc.y += yu.y;
        }
        float tx = fmaxf(sm * acc.x, 0.f);
        float ty = fmaxf(sm * acc.y, 0.f);
        float g = tx * sW2[2 * lane] + ty * sW2[2 * lane + 1];
#pragma unroll
        for (int off = 16; off; off >>= 1) g += __shfl_xor_sync(0xffffffffu, g, off);
        if (lane == 0) sG[m] = sm * g;
    }
    __syncthreads();

    // h2 at nodes i and j ; out = h2[i] + h2[j]
    if (warp == 0) {
        float res = 0.f;
#pragma unroll
        for (int e = 0; e < 2; e++) {
            int k = e ? j : i;
            int lim = (k == U) ? L : U;
            unsigned w0 = sMask[k * 3 + 0] & wmask(lim, 0);
            unsigned w1 = sMask[k * 3 + 1] & wmask(lim, 1);
            unsigned w2 = sMask[k * 3 + 2] & wmask(lim, 2);
            float v = 0.f;
            if ((w0 >> lane) & 1) v += sG[lane];
            if ((w1 >> lane) & 1) v += sG[32 + lane];
            if ((w2 >> lane) & 1) v += sG[64 + lane];
#pragma unroll
            for (int off = 16; off; off >>= 1) v += __shfl_xor_sync(0xffffffffu, v, off);
            v += sG[k];  // self loop
            if (k < L && ((sMask[U * 3 + (k >> 5)] >> (k & 31)) & 1)) v += sG[U];
            res += sS[k] * v;
        }
        if (lane == 0) out[p] = res;
    }
}

extern "C" void kernel_launch(void* const* d_in, const int* in_sizes, int n_in,
                              void* d_out, int out_size) {
    const float* z   = (const float*)d_in[0];
    const float* adj = (const float*)d_in[1];
    const float* W1  = (const float*)d_in[2];
    const float* W2  = (const float*)d_in[3];
    float* out = (float*)d_out;

    setup_x0_kernel<<<NN, DD>>>(z, W1);
    setup_adj_kernel<<<NN, NN>>>(adj);
    pair_kernel<<<NN * NN, 128>>>(W1, W2, out);
}

// round 2
// speedup vs baseline: 1.7020x; 1.7020x over previous
#include <cuda_runtime.h>
#include <cstdint>

#define NN 96
#define DD 64
#define NPAIRS ((NN * (NN + 1)) / 2)   // 4656 unordered pairs (L <= U)

// Scratch (allocation-free rule): device globals, recomputed deterministically every launch.
__device__ float g_X0[NN * DD];                        // z @ W1[:64]
__device__ unsigned g_mask[NN * 3];                    // adjacency bitmask rows
__device__ __align__(16) unsigned char g_nbr[NN * NN]; // sorted neighbor lists

__global__ void setup_x0_kernel(const float* __restrict__ z, const float* __restrict__ W1) {
    int row = blockIdx.x, c = threadIdx.x;   // 96 blocks x 64 threads
    __shared__ float zr[DD];
    zr[c] = z[row * DD + c];
    __syncthreads();
    float acc = 0.f;
#pragma unroll
    for (int k = 0; k < DD; k++) acc += zr[k] * W1[k * DD + c];
    g_X0[row * DD + c] = acc;
}

__global__ void setup_adj_kernel(const float* __restrict__ adj) {
    int row = blockIdx.x;                    // 96 blocks x 96 threads
    int t = threadIdx.x;
    __shared__ unsigned char flag[NN];
    flag[t] = (adj[row * NN + t] != 0.0f) ? 1 : 0;
    __syncthreads();
    unsigned bal = __ballot_sync(0xffffffffu, flag[t] != 0);
    if ((t & 31) == 0) g_mask[row * 3 + (t >> 5)] = bal;
    if (t == 0) {
        int c = 0;
        for (int b = 0; b < NN; b++)
            if (flag[b]) g_nbr[row * NN + c++] = (unsigned char)b;
        for (; c < NN; c++) g_nbr[row * NN + c] = 96;  // pad with zero-row index
    }
}

// bits [0, n) of 32-bit word w
__device__ __forceinline__ unsigned wmask(int n, int w) {
    int m = n - (w << 5);
    if (m <= 0) return 0u;
    if (m >= 32) return 0xffffffffu;
    return (1u << m) - 1u;
}

// packed fp32x2 add (Blackwell)
__device__ __forceinline__ unsigned long long f2add(unsigned long long a, unsigned long long b) {
    unsigned long long r;
    asm("add.rn.f32x2 %0, %1, %2;" : "=l"(r) : "l"(a), "l"(b));
    return r;
}

__global__ void __launch_bounds__(128) pair_kernel(const float* __restrict__ W1,
                                                   const float* __restrict__ W2,
                                                   float* __restrict__ out) {
    __shared__ float sY[(NN + 1) * DD]; // scaled, perturbed rows; row 96 = zeros (padding)
    __shared__ float sS[NN];            // deg^-1/2
    __shared__ float sG1[NN];           // s_m * (h1 . W2), pair (L,U)
    __shared__ float sG2[NN];           // pair (U,L)
    __shared__ int sCnt[NN];
    __shared__ unsigned sMask[NN * 3];
    __shared__ __align__(16) unsigned char sNbr[NN * NN];
    __shared__ float sW2[DD];

    // triangular decode, reversed so heavy (large U) CTAs launch first
    int t = (NPAIRS - 1) - (int)blockIdx.x;
    int U = (int)((sqrtf(8.0f * (float)t + 1.0f) - 1.0f) * 0.5f);
    while ((U + 1) * (U + 2) / 2 <= t) ++U;
    while (U * (U + 1) / 2 > t) --U;
    int L = t - U * (U + 1) / 2;

    int tid = threadIdx.x;
    int lane = tid & 31, warp = tid >> 5;

    for (int q = tid; q < NN * 3; q += 128) sMask[q] = g_mask[q];
    int nb4 = (U + 1) * 6;   // rows 0..U, 6 uint4 per 96-byte row
    for (int q = tid; q < nb4; q += 128)
        ((uint4*)sNbr)[q] = ((const uint4*)g_nbr)[q];
    if (tid < DD) sW2[tid] = W2[tid];
    if (tid < 16) ((float4*)sY)[NN * 16 + tid] = make_float4(0.f, 0.f, 0.f, 0.f); // zero row
    __syncthreads();

    // degrees / scales for nodes 0..U
    if (tid <= U) {
        int k = tid;
        int lim = (k == U) ? L : U;   // node U only links to neighbors < L
        unsigned m0 = sMask[k * 3 + 0] & wmask(lim, 0);
        unsigned m1 = sMask[k * 3 + 1] & wmask(lim, 1);
        unsigned m2 = sMask[k * 3 + 2] & wmask(lim, 2);
        int cnt = __popc(m0) + __popc(m1) + __popc(m2);
        int deg = 1 + cnt;   // self loop
        if (k < L) deg += (sMask[U * 3 + (k >> 5)] >> (k & 31)) & 1;  // edge to U
        sS[k] = rsqrtf((float)deg);
        sCnt[k] = cnt;
    }
    __syncthreads();

    float sL = sS[L], sU = sS[U];

    // build Y rows 0..U for pair1=(L,U): row L += W1[64], row U += W1[65], scaled by s_row
    int n4 = (U + 1) * (DD / 4);
    const float4* x04 = (const float4*)g_X0;
    for (int q = tid; q < n4; q += 128) {
        int row = q >> 4;
        int cb = (q & 15) * 4;
        float4 v = x04[q];
        if (row == L) {
            v.x += W1[64 * DD + cb + 0]; v.y += W1[64 * DD + cb + 1];
            v.z += W1[64 * DD + cb + 2]; v.w += W1[64 * DD + cb + 3];
        }
        if (row == U) {
            v.x += W1[65 * DD + cb + 0]; v.y += W1[65 * DD + cb + 1];
            v.z += W1[65 * DD + cb + 2]; v.w += W1[65 * DD + cb + 3];
        }
        float s = sS[row];
        v.x *= s; v.y *= s; v.z *= s; v.w *= s;
        ((float4*)sY)[q] = v;
    }
    __syncthreads();

    // per-lane constants
    float w2x = sW2[2 * lane], w2y = sW2[2 * lane + 1];
    float dx = W1[65 * DD + 2 * lane]     - W1[64 * DD + 2 * lane];
    float dy = W1[65 * DD + 2 * lane + 1] - W1[64 * DD + 2 * lane + 1];

    // h1 = relu(conv(Y)); g = s_m * (h1 . W2) for both mirrored pairs
    const unsigned long long* Yu = (const unsigned long long*)sY;
    for (int m = warp; m <= U; m += 4) {
        float sm = sS[m];
        unsigned long long acc0 = Yu[(m << 5) + lane];   // self term
        unsigned long long acc1 = 0ull;
        if (m < L && ((sMask[U * 3 + (m >> 5)] >> (m & 31)) & 1))
            acc1 = Yu[(U << 5) + lane];                  // extra edge to U

        int cnt = sCnt[m];
        const unsigned char* lst = &sNbr[m * NN];
        int fullc = cnt & ~3;
        int q = 0;
        for (; q < fullc; q += 4) {
            unsigned pk = *(const unsigned*)(lst + q);
            acc0 = f2add(acc0, Yu[((pk & 255u) << 5) + lane]);
            acc1 = f2add(acc1, Yu[(((pk >> 8) & 255u) << 5) + lane]);
            acc0 = f2add(acc0, Yu[(((pk >> 16) & 255u) << 5) + lane]);
            acc1 = f2add(acc1, Yu[((pk >> 24) << 5) + lane]);
        }
        int rem = cnt - fullc;
        if (rem) {
            unsigned pk = *(const unsigned*)(lst + q);
            unsigned b0 = pk & 255u;
            unsigned b1 = (rem > 1) ? ((pk >> 8) & 255u) : 96u;
            unsigned b2 = (rem > 2) ? ((pk >> 16) & 255u) : 96u;
            acc0 = f2add(acc0, Yu[(b0 << 5) + lane]);
            acc1 = f2add(acc1, Yu[(b1 << 5) + lane]);
            acc0 = f2add(acc0, Yu[(b2 << 5) + lane]);
        }
        unsigned long long acc = f2add(acc0, acc1);
        float ax = __uint_as_float((unsigned)acc);
        float ay = __uint_as_float((unsigned)(acc >> 32));

        // c_m = A[m,L]*sL - A[m,U]*sU  (pair2 = pair1 + c_m * d)
        float c = 0.f;
        if (L != U) {
            if (m == U) c = -sU;
            else {
                unsigned aL = ((sMask[L * 3 + (m >> 5)] >> (m & 31)) & 1) | (unsigned)(m == L);
                c = aL ? sL : 0.f;
                if (m < L && ((sMask[U * 3 + (m >> 5)] >> (m & 31)) & 1)) c -= sU;
            }
        }
        float g1 = fmaxf(sm * ax, 0.f) * w2x + fmaxf(sm * ay, 0.f) * w2y;
        float a2x = ax + c * dx, a2y = ay + c * dy;
        float g2 = fmaxf(sm * a2x, 0.f) * w2x + fmaxf(sm * a2y, 0.f) * w2y;
#pragma unroll
        for (int off = 16; off; off >>= 1) {
            g1 += __shfl_xor_sync(0xffffffffu, g1, off);
            g2 += __shfl_xor_sync(0xffffffffu, g2, off);
        }
        if (lane == 0) { sG1[m] = sm * g1; sG2[m] = sm * g2; }
    }
    __syncthreads();

    // second conv layer at nodes L and U; out = h2[i] + h2[j]
    if (warp < 2) {
        const float* G = warp ? sG2 : sG1;
        float res = 0.f;
#pragma unroll
        for (int e = 0; e < 2; e++) {
            int k = e ? U : L;
            int lim = (k == U) ? L : U;
            unsigned w0 = sMask[k * 3 + 0] & wmask(lim, 0);
            unsigned w1 = sMask[k * 3 + 1] & wmask(lim, 1);
            unsigned w2 = sMask[k * 3 + 2] & wmask(lim, 2);
            float v = 0.f;
            if ((w0 >> lane) & 1) v += G[lane];
            if ((w1 >> lane) & 1) v += G[32 + lane];
            if ((w2 >> lane) & 1) v += G[64 + lane];
#pragma unroll
            for (int off = 16; off; off >>= 1) v += __shfl_xor_sync(0xffffffffu, v, off);
            v += G[k];  // self loop
            if (k < L && ((sMask[U * 3 + (k >> 5)] >> (k & 31)) & 1)) v += G[U];
            res += sS[k] * v;
        }
        if (lane == 0) out[warp ? (U * NN + L) : (L * NN + U)] = res;
    }
}

extern "C" void kernel_launch(void* const* d_in, const int* in_sizes, int n_in,
                              void* d_out, int out_size) {
    const float* z   = (const float*)d_in[0];
    const float* adj = (const float*)d_in[1];
    const float* W1  = (const float*)d_in[2];
    const float* W2  = (const float*)d_in[3];
    float* out = (float*)d_out;

    setup_x0_kernel<<<NN, DD>>>(z, W1);
    setup_adj_kernel<<<NN, NN>>>(adj);
    pair_kernel<<<NPAIRS, 128>>>(W1, W2, out);
}

// round 3
// speedup vs baseline: 1.8770x; 1.1028x over previous
#include <cuda_runtime.h>
#include <cstdint>

#define NN 96
#define DD 64
#define NPAIRS ((NN * (NN + 1)) / 2)   // 4656 unordered pairs (L <= U)
#define TPB 256
#define NWARP 8

// Scratch (allocation-free rule): device globals, recomputed deterministically every launch.
__device__ float g_X0[NN * DD];                        // z @ W1[:64]
__device__ unsigned g_mask[NN * 3];                    // adjacency bitmask rows
__device__ __align__(16) unsigned char g_nbr[NN * NN]; // sorted neighbor lists

// blocks 0..95: X0 row; blocks 96..191: adjacency row
__global__ void setup_kernel(const float* __restrict__ z, const float* __restrict__ W1,
                             const float* __restrict__ adj) {
    if (blockIdx.x < NN) {
        int row = blockIdx.x, c = threadIdx.x;
        __shared__ float zr[DD];
        if (c < DD) zr[c] = z[row * DD + c];
        __syncthreads();
        if (c < DD) {
            float acc = 0.f;
#pragma unroll
            for (int k = 0; k < DD; k++) acc += zr[k] * W1[k * DD + c];
            g_X0[row * DD + c] = acc;
        }
    } else {
        int row = blockIdx.x - NN;
        int t = threadIdx.x;
        __shared__ unsigned char flag[NN];
        flag[t] = (adj[row * NN + t] != 0.0f) ? 1 : 0;
        __syncthreads();
        unsigned bal = __ballot_sync(0xffffffffu, flag[t] != 0);
        if ((t & 31) == 0) g_mask[row * 3 + (t >> 5)] = bal;
        if (t == 0) {
            int c = 0;
            for (int b = 0; b < NN; b++)
                if (flag[b]) g_nbr[row * NN + c++] = (unsigned char)b;
            for (; c < NN; c++) g_nbr[row * NN + c] = 96;  // pad with zero-row index
        }
    }
}

// bits [0, n) of 32-bit word w
__device__ __forceinline__ unsigned wmask(int n, int w) {
    int m = n - (w << 5);
    if (m <= 0) return 0u;
    if (m >= 32) return 0xffffffffu;
    return (1u << m) - 1u;
}

// packed fp32x2 add (Blackwell)
__device__ __forceinline__ unsigned long long f2add(unsigned long long a, unsigned long long b) {
    unsigned long long r;
    asm("add.rn.f32x2 %0, %1, %2;" : "=l"(r) : "l"(a), "l"(b));
    return r;
}

__global__ void __launch_bounds__(TPB) pair_kernel(const float* __restrict__ W1,
                                                   const float* __restrict__ W2,
                                                   float* __restrict__ out) {
    __shared__ float sY[(NN + 1) * DD]; // scaled, perturbed rows; row 96 = zeros (padding)
    __shared__ float sS[NN];            // deg^-1/2
    __shared__ float sG1[NN];           // s_m * (h1 . W2), pair (L,U)
    __shared__ float sG2[NN];           // pair (U,L)
    __shared__ int sCnt[NN];
    __shared__ unsigned sMask[NN * 3];
    __shared__ __align__(16) unsigned char sNbr[NN * NN];
    __shared__ float sW2[DD];

    // triangular decode, reversed so heavy (large U) CTAs launch first
    int t = (NPAIRS - 1) - (int)blockIdx.x;
    int U = (int)((sqrtf(8.0f * (float)t + 1.0f) - 1.0f) * 0.5f);
    while ((U + 1) * (U + 2) / 2 <= t) ++U;
    while (U * (U + 1) / 2 > t) --U;
    int L = t - U * (U + 1) / 2;

    int tid = threadIdx.x;
    int lane = tid & 31, warp = tid >> 5;

    for (int q = tid; q < NN * 3; q += TPB) sMask[q] = g_mask[q];
    int nb4 = (U + 1) * 6;   // rows 0..U, 6 uint4 per 96-byte row
    for (int q = tid; q < nb4; q += TPB)
        ((uint4*)sNbr)[q] = ((const uint4*)g_nbr)[q];
    if (tid < DD) sW2[tid] = W2[tid];
    if (tid < 16) ((float4*)sY)[NN * 16 + tid] = make_float4(0.f, 0.f, 0.f, 0.f); // zero row
    __syncthreads();

    // degrees / scales for nodes 0..U
    if (tid <= U) {
        int k = tid;
        int lim = (k == U) ? L : U;   // node U only links to neighbors < L
        unsigned m0 = sMask[k * 3 + 0] & wmask(lim, 0);
        unsigned m1 = sMask[k * 3 + 1] & wmask(lim, 1);
        unsigned m2 = sMask[k * 3 + 2] & wmask(lim, 2);
        int cnt = __popc(m0) + __popc(m1) + __popc(m2);
        int deg = 1 + cnt;   // self loop
        if (k < L) deg += (sMask[U * 3 + (k >> 5)] >> (k & 31)) & 1;  // edge to U
        sS[k] = rsqrtf((float)deg);
        sCnt[k] = cnt;
    }
    __syncthreads();

    float sL = sS[L], sU = sS[U];

    // build Y rows 0..U for pair1=(L,U): row L += W1[64], row U += W1[65], scaled by s_row
    int n4 = (U + 1) * (DD / 4);
    const float4* x04 = (const float4*)g_X0;
    for (int q = tid; q < n4; q += TPB) {
        int row = q >> 4;
        int cb = (q & 15) * 4;
        float4 v = x04[q];
        if (row == L) {
            v.x += W1[64 * DD + cb + 0]; v.y += W1[64 * DD + cb + 1];
            v.z += W1[64 * DD + cb + 2]; v.w += W1[64 * DD + cb + 3];
        }
        if (row == U) {
            v.x += W1[65 * DD + cb + 0]; v.y += W1[65 * DD + cb + 1];
            v.z += W1[65 * DD + cb + 2]; v.w += W1[65 * DD + cb + 3];
        }
        float s = sS[row];
        v.x *= s; v.y *= s; v.z *= s; v.w *= s;
        ((float4*)sY)[q] = v;
    }
    __syncthreads();

    // per-lane constants
    float w2x = sW2[2 * lane], w2y = sW2[2 * lane + 1];
    float dx = W1[65 * DD + 2 * lane]     - W1[64 * DD + 2 * lane];
    float dy = W1[65 * DD + 2 * lane + 1] - W1[64 * DD + 2 * lane + 1];

    // h1 = relu(conv(Y)); g = s_m * (h1 . W2) for both mirrored pairs
    const unsigned long long* Yu = (const unsigned long long*)sY;
    for (int m = warp; m <= U; m += NWARP) {
        float sm = sS[m];
        unsigned long long acc0 = Yu[(m << 5) + lane];   // self term
        unsigned long long acc1 = 0ull;
        if (m < L && ((sMask[U * 3 + (m >> 5)] >> (m & 31)) & 1))
            acc1 = Yu[(U << 5) + lane];                  // extra edge to U

        int cnt = sCnt[m];
        const unsigned char* lst = &sNbr[m * NN];
        int fullc = cnt & ~3;
        int q = 0;
        for (; q < fullc; q += 4) {
            unsigned pk = *(const unsigned*)(lst + q);
            acc0 = f2add(acc0, Yu[((pk & 255u) << 5) + lane]);
            acc1 = f2add(acc1, Yu[(((pk >> 8) & 255u) << 5) + lane]);
            acc0 = f2add(acc0, Yu[(((pk >> 16) & 255u) << 5) + lane]);
            acc1 = f2add(acc1, Yu[((pk >> 24) << 5) + lane]);
        }
        int rem = cnt - fullc;
        if (rem) {
            unsigned pk = *(const unsigned*)(lst + q);
            unsigned b0 = pk & 255u;
            unsigned b1 = (rem > 1) ? ((pk >> 8) & 255u) : 96u;
            unsigned b2 = (rem > 2) ? ((pk >> 16) & 255u) : 96u;
            acc0 = f2add(acc0, Yu[(b0 << 5) + lane]);
            acc1 = f2add(acc1, Yu[(b1 << 5) + lane]);
            acc0 = f2add(acc0, Yu[(b2 << 5) + lane]);
        }
        unsigned long long acc = f2add(acc0, acc1);
        float ax = __uint_as_float((unsigned)acc);
        float ay = __uint_as_float((unsigned)(acc >> 32));

        // c_m = A[m,L]*sL - A[m,U]*sU  (pair2 = pair1 + c_m * d)
        float c = 0.f;
        if (L != U) {
            if (m == U) c = -sU;
            else {
                unsigned aL = ((sMask[L * 3 + (m >> 5)] >> (m & 31)) & 1) | (unsigned)(m == L);
                c = aL ? sL : 0.f;
                if (m < L && ((sMask[U * 3 + (m >> 5)] >> (m & 31)) & 1)) c -= sU;
            }
        }
        float g1 = fmaxf(sm * ax, 0.f) * w2x + fmaxf(sm * ay, 0.f) * w2y;
        float a2x = ax + c * dx, a2y = ay + c * dy;
        float g2 = fmaxf(sm * a2x, 0.f) * w2x + fmaxf(sm * a2y, 0.f) * w2y;
#pragma unroll
        for (int off = 16; off; off >>= 1) {
            g1 += __shfl_xor_sync(0xffffffffu, g1, off);
            g2 += __shfl_xor_sync(0xffffffffu, g2, off);
        }
        if (lane == 0) { sG1[m] = sm * g1; sG2[m] = sm * g2; }
    }
    __syncthreads();

    // second conv layer at nodes L and U; out = h2[i] + h2[j]
    if (warp < 2) {
        const float* G = warp ? sG2 : sG1;
        float res = 0.f;
#pragma unroll
        for (int e = 0; e < 2; e++) {
            int k = e ? U : L;
            int lim = (k == U) ? L : U;
            unsigned w0 = sMask[k * 3 + 0] & wmask(lim, 0);
            unsigned w1 = sMask[k * 3 + 1] & wmask(lim, 1);
            unsigned w2 = sMask[k * 3 + 2] & wmask(lim, 2);
            float v = 0.f;
            if ((w0 >> lane) & 1) v += G[lane];
            if ((w1 >> lane) & 1) v += G[32 + lane];
            if ((w2 >> lane) & 1) v += G[64 + lane];
#pragma unroll
            for (int off = 16; off; off >>= 1) v += __shfl_xor_sync(0xffffffffu, v, off);
            v += G[k];  // self loop
            if (k < L && ((sMask[U * 3 + (k >> 5)] >> (k & 31)) & 1)) v += G[U];
            res += sS[k] * v;
        }
        if (lane == 0) out[warp ? (U * NN + L) : (L * NN + U)] = res;
    }
}

extern "C" void kernel_launch(void* const* d_in, const int* in_sizes, int n_in,
                              void* d_out, int out_size) {
    const float* z   = (const float*)d_in[0];
    const float* adj = (const float*)d_in[1];
    const float* W1  = (const float*)d_in[2];
    const float* W2  = (const float*)d_in[3];
    float* out = (float*)d_out;

    setup_kernel<<<2 * NN, NN>>>(z, W1, adj);
    pair_kernel<<<NPAIRS, TPB>>>(W1, W2, out);
}

// round 4
// speedup vs baseline: 2.0912x; 1.1141x over previous
#include <cuda_runtime.h>
#include <cstdint>

#define NN 96
#define DD 64
#define NPAIRS ((NN * (NN + 1)) / 2)   // 4656 unordered pairs (L <= U)
#define TPB 256
#define NWARP 8

// Scratch (allocation-free rule): device globals, recomputed deterministically every launch.
__device__ float g_X0[NN * DD];                        // z @ W1[:64]
__device__ unsigned g_mask[NN * 3];                    // adjacency bitmask rows
__device__ __align__(16) unsigned char g_nbr[NN * NN]; // sorted neighbor lists

// blocks 0..95: X0 row; blocks 96..191: adjacency row
__global__ void setup_kernel(const float* __restrict__ z, const float* __restrict__ W1,
                             const float* __restrict__ adj) {
    if (blockIdx.x < NN) {
        int row = blockIdx.x, c = threadIdx.x;
        __shared__ float zr[DD];
        if (c < DD) zr[c] = z[row * DD + c];
        __syncthreads();
        if (c < DD) {
            float acc = 0.f;
#pragma unroll
            for (int k = 0; k < DD; k++) acc += zr[k] * W1[k * DD + c];
            g_X0[row * DD + c] = acc;
        }
    } else {
        int row = blockIdx.x - NN;
        int t = threadIdx.x;
        __shared__ unsigned char flag[NN];
        flag[t] = (adj[row * NN + t] != 0.0f) ? 1 : 0;
        __syncthreads();
        unsigned bal = __ballot_sync(0xffffffffu, flag[t] != 0);
        if ((t & 31) == 0) g_mask[row * 3 + (t >> 5)] = bal;
        if (t == 0) {
            int c = 0;
            for (int b = 0; b < NN; b++)
                if (flag[b]) g_nbr[row * NN + c++] = (unsigned char)b;
            for (; c < NN; c++) g_nbr[row * NN + c] = 96;  // pad with zero-row index
        }
    }
}

// bits [0, n) of 32-bit word w
__device__ __forceinline__ unsigned wmask(int n, int w) {
    int m = n - (w << 5);
    if (m <= 0) return 0u;
    if (m >= 32) return 0xffffffffu;
    return (1u << m) - 1u;
}

// packed fp32x2 add (Blackwell)
__device__ __forceinline__ unsigned long long f2add(unsigned long long a, unsigned long long b) {
    unsigned long long r;
    asm("add.rn.f32x2 %0, %1, %2;" : "=l"(r) : "l"(a), "l"(b));
    return r;
}

__global__ void __launch_bounds__(TPB) pair_kernel(const float* __restrict__ W1,
                                                   const float* __restrict__ W2,
                                                   float* __restrict__ out) {
    __shared__ float sY[(NN + 1) * DD]; // scaled, perturbed rows; rows >= U are ZERO; row 96 zero pad
    __shared__ float sS[NN];            // deg^-1/2
    __shared__ float sG1[NN];           // s_m * (h1 . W2), pair (L,U)
    __shared__ float sG2[NN];           // pair (U,L)
    __shared__ int sCnt[NN];
    __shared__ unsigned sMask[NN * 3];
    __shared__ __align__(16) unsigned char sNbr[(NN + 1) * NN]; // row 96 = all-96 (idle list)
    __shared__ float sW2[DD];

    // triangular decode, reversed so heavy (large U) CTAs launch first
    int t = (NPAIRS - 1) - (int)blockIdx.x;
    int U = (int)((sqrtf(8.0f * (float)t + 1.0f) - 1.0f) * 0.5f);
    while ((U + 1) * (U + 2) / 2 <= t) ++U;
    while (U * (U + 1) / 2 > t) --U;
    int L = t - U * (U + 1) / 2;

    int tid = threadIdx.x;
    int lane = tid & 31, warp = tid >> 5;
    int h = lane >> 4, ln = lane & 15;

    for (int q = tid; q < NN * 3; q += TPB) sMask[q] = g_mask[q];
    int nb4 = (U + 1) * 6;   // rows 0..U, 6 uint4 per 96-byte row
    for (int q = tid; q < nb4; q += TPB)
        ((uint4*)sNbr)[q] = ((const uint4*)g_nbr)[q];
    if (tid < 24) ((unsigned*)sNbr)[NN * 24 + tid] = 0x60606060u;  // row 96: all point at zero row
    if (tid < DD) sW2[tid] = W2[tid];
    __syncthreads();

    // degrees / scales for nodes 0..U
    if (tid <= U) {
        int k = tid;
        int lim = (k == U) ? L : U;   // node U only links to neighbors < L
        unsigned m0 = sMask[k * 3 + 0] & wmask(lim, 0);
        unsigned m1 = sMask[k * 3 + 1] & wmask(lim, 1);
        unsigned m2 = sMask[k * 3 + 2] & wmask(lim, 2);
        int cnt = __popc(m0) + __popc(m1) + __popc(m2);
        int deg = 1 + cnt;   // self loop
        if (k < L) deg += (sMask[U * 3 + (k >> 5)] >> (k & 31)) & 1;  // edge to U
        sS[k] = rsqrtf((float)deg);
        sCnt[k] = cnt;
    }
    __syncthreads();

    float sL = sS[L], sU = sS[U];
    const float4* x04 = (const float4*)g_X0;
    const float4* W14 = (const float4*)W1;

    // build Y rows: 0..U-1 = s_row*(X0 + [row==L] W1[64]); rows U..96 = 0 (Y_U lives in registers)
    for (int q = tid; q < (NN + 1) * 16; q += TPB) {
        int row = q >> 4;
        float4 v = make_float4(0.f, 0.f, 0.f, 0.f);
        if (row < U) {
            v = x04[q];
            if (row == L) {
                float4 p = W14[64 * 16 + (q & 15)];
                v.x += p.x; v.y += p.y; v.z += p.z; v.w += p.w;
            }
            float s = sS[row];
            v.x *= s; v.y *= s; v.z *= s; v.w *= s;
        }
        ((float4*)sY)[q] = v;
    }

    // per-lane constants (float4-slice layout, cols ln*4..ln*4+3)
    float4 w2v = ((const float4*)sW2)[ln];   // note: sW2 written pre-sync above; sync below covers
    float4 pa = W14[64 * 16 + ln];
    float4 pb = W14[65 * 16 + ln];
    float4 dv = make_float4(pb.x - pa.x, pb.y - pa.y, pb.z - pa.z, pb.w - pa.w);
    float4 u4 = x04[U * 16 + ln];
    u4.x += pb.x; u4.y += pb.y; u4.z += pb.z; u4.w += pb.w;
    if (L == U) { u4.x += pa.x; u4.y += pa.y; u4.z += pa.z; u4.w += pa.w; }
    u4.x *= sU; u4.y *= sU; u4.z *= sU; u4.w *= sU;
    unsigned long long uLo, uHi;
    { ulonglong2 tmp = *(ulonglong2*)&u4; uLo = tmp.x; uHi = tmp.y; }
    __syncthreads();

    const ulonglong2* Yu2 = (const ulonglong2*)sY;   // index = row*16 + ln

    // ---- paired gather: nodes 0..U-1, two nodes per warp (one per half-warp) ----
    for (int mb = 0; mb < U; mb += 16) {
        int m = mb + 2 * warp + h;
        bool act = (m < U);
        int mrow = act ? m : NN;                 // idle half -> synthetic all-96 list + zero row
        int cnt = act ? sCnt[m] : 0;
        int cmax = max(cnt, __shfl_xor_sync(0xffffffffu, cnt, 16));
        cmax = (cmax + 3) & ~3;

        ulonglong2 seed = Yu2[mrow * 16 + ln];   // self term (zero row if idle)
        unsigned long long a0 = seed.x, b0 = seed.y;
        unsigned long long a1 = 0ull, b1 = 0ull;
        if (act && m < L && ((sMask[U * 3 + (m >> 5)] >> (m & 31)) & 1)) { a1 = uLo; b1 = uHi; }

        const unsigned char* lst = sNbr + mrow * NN;
        for (int q = 0; q < cmax; q += 4) {
            unsigned pk = *(const unsigned*)(lst + q);
            ulonglong2 y0 = Yu2[((pk & 255u) << 4) + ln];
            a0 = f2add(a0, y0.x); b0 = f2add(b0, y0.y);
            ulonglong2 y1 = Yu2[(((pk >> 8) & 255u) << 4) + ln];
            a1 = f2add(a1, y1.x); b1 = f2add(b1, y1.y);
            ulonglong2 y2 = Yu2[(((pk >> 16) & 255u) << 4) + ln];
            a0 = f2add(a0, y2.x); b0 = f2add(b0, y2.y);
            ulonglong2 y3 = Yu2[((pk >> 24) << 4) + ln];
            a1 = f2add(a1, y3.x); b1 = f2add(b1, y3.y);
        }
        a0 = f2add(a0, a1); b0 = f2add(b0, b1);
        float v0 = __uint_as_float((unsigned)a0), v1 = __uint_as_float((unsigned)(a0 >> 32));
        float v2 = __uint_as_float((unsigned)b0), v3 = __uint_as_float((unsigned)(b0 >> 32));

        float sm = act ? sS[m] : 0.f;
        // c_m = A[m,L]*sL - A[m,U]*sU   (pair2 presum = pair1 + c_m * d)
        float c = 0.f;
        if (act && L != U) {
            unsigned aL = ((sMask[L * 3 + (m >> 5)] >> (m & 31)) & 1) | (unsigned)(m == L);
            c = aL ? sL : 0.f;
            if (m < L && ((sMask[U * 3 + (m >> 5)] >> (m & 31)) & 1)) c -= sU;
        }
        float g1 = fmaxf(sm * v0, 0.f) * w2v.x + fmaxf(sm * v1, 0.f) * w2v.y
                 + fmaxf(sm * v2, 0.f) * w2v.z + fmaxf(sm * v3, 0.f) * w2v.w;
        float g2 = fmaxf(sm * (v0 + c * dv.x), 0.f) * w2v.x
                 + fmaxf(sm * (v1 + c * dv.y), 0.f) * w2v.y
                 + fmaxf(sm * (v2 + c * dv.z), 0.f) * w2v.z
                 + fmaxf(sm * (v3 + c * dv.w), 0.f) * w2v.w;
#pragma unroll
        for (int off = 1; off < 16; off <<= 1) {
            g1 += __shfl_xor_sync(0xffffffffu, g1, off);
            g2 += __shfl_xor_sync(0xffffffffu, g2, off);
        }
        if (act && ln == 0) { sG1[m] = sm * g1; sG2[m] = sm * g2; }
    }

    // ---- dedicated handling of node U (full warp 7, 2 floats/lane, masked by cnt) ----
    if (warp == 7) {
        int c2 = 2 * lane;
        float ux = g_X0[U * DD + c2]     + W1[65 * DD + c2];
        float uy = g_X0[U * DD + c2 + 1] + W1[65 * DD + c2 + 1];
        if (L == U) { ux += W1[64 * DD + c2]; uy += W1[64 * DD + c2 + 1]; }
        float ax = sU * ux, ay = sU * uy;
        int cnt = sCnt[U];    // neighbors < L (list prefix)
        const unsigned char* lst = sNbr + U * NN;
        const float2* Y2 = (const float2*)sY;
        for (int q = 0; q < cnt; q++) {
            int b = lst[q];
            float2 yb = Y2[b * 32 + lane];
            ax += yb.x; ay += yb.y;
        }
        float c = (L != U) ? -sU : 0.f;
        float w2x = sW2[c2], w2y = sW2[c2 + 1];
        float dx = W1[65 * DD + c2]     - W1[64 * DD + c2];
        float dy = W1[65 * DD + c2 + 1] - W1[64 * DD + c2 + 1];
        float g1 = fmaxf(sU * ax, 0.f) * w2x + fmaxf(sU * ay, 0.f) * w2y;
        float g2 = fmaxf(sU * (ax + c * dx), 0.f) * w2x + fmaxf(sU * (ay + c * dy), 0.f) * w2y;
#pragma unroll
        for (int off = 16; off; off >>= 1) {
            g1 += __shfl_xor_sync(0xffffffffu, g1, off);
            g2 += __shfl_xor_sync(0xffffffffu, g2, off);
        }
        if (lane == 0) { sG1[U] = sU * g1; sG2[U] = sU * g2; }
    }
    __syncthreads();

    // second conv layer at nodes L and U; out = h2[i] + h2[j]
    if (warp < 2) {
        const float* G = warp ? sG2 : sG1;
        float res = 0.f;
#pragma unroll
        for (int e = 0; e < 2; e++) {
            int k = e ? U : L;
            int lim = (k == U) ? L : U;
            unsigned w0 = sMask[k * 3 + 0] & wmask(lim, 0);
            unsigned w1 = sMask[k * 3 + 1] & wmask(lim, 1);
            unsigned w2 = sMask[k * 3 + 2] & wmask(lim, 2);
            float v = 0.f;
            if ((w0 >> lane) & 1) v += G[lane];
            if ((w1 >> lane) & 1) v += G[32 + lane];
            if ((w2 >> lane) & 1) v += G[64 + lane];
#pragma unroll
            for (int off = 16; off; off >>= 1) v += __shfl_xor_sync(0xffffffffu, v, off);
            v += G[k];  // self loop
            if (k < L && ((sMask[U * 3 + (k >> 5)] >> (k & 31)) & 1)) v += G[U];
            res += sS[k] * v;
        }
        if (lane == 0) out[warp ? (U * NN + L) : (L * NN + U)] = res;
    }
}

extern "C" void kernel_launch(void* const* d_in, const int* in_sizes, int n_in,
                              void* d_out, int out_size) {
    const float* z   = (const float*)d_in[0];
    const float* adj = (const float*)d_in[1];
    const float* W1  = (const float*)d_in[2];
    const float* W2  = (const float*)d_in[3];
    float* out = (float*)d_out;

    setup_kernel<<<2 * NN, NN>>>(z, W1, adj);
    pair_kernel<<<NPAIRS, TPB>>>(W1, W2, out);
}

// round 5
// speedup vs baseline: 3.6243x; 1.7331x over previous
#include <cuda_runtime.h>
#include <cstdint>

#define NN 96
#define DD 64
#define NPAIRS ((NN * (NN + 1)) / 2)   // 4656 unordered pairs (L <= U)
#define TPB 256

// Scratch (allocation-free rule): device globals, recomputed deterministically every launch.
__device__ float g_X0[NN * DD];                        // z @ W1[:64]
__device__ float g_P0[NN * NN * DD];                   // [U][m][64]: base pre-activations
__device__ unsigned g_mask[NN * 3];                    // adjacency bitmask rows
__device__ __align__(16) unsigned char g_nbr[NN * NN]; // sorted neighbor lists

// bits [0, n) of 32-bit word w
__device__ __forceinline__ unsigned wmask(int n, int w) {
    int m = n - (w << 5);
    if (m <= 0) return 0u;
    if (m >= 32) return 0xffffffffu;
    return (1u << m) - 1u;
}

// blocks 0..95: X0 row; blocks 96..191: adjacency row
__global__ void setup_kernel(const float* __restrict__ z, const float* __restrict__ W1,
                             const float* __restrict__ adj) {
    if (blockIdx.x < NN) {
        int row = blockIdx.x, c = threadIdx.x;
        __shared__ float zr[DD];
        if (c < DD) zr[c] = z[row * DD + c];
        __syncthreads();
        if (c < DD) {
            float acc = 0.f;
#pragma unroll
            for (int k = 0; k < DD; k++) acc += zr[k] * W1[k * DD + c];
            g_X0[row * DD + c] = acc;
        }
    } else {
        int row = blockIdx.x - NN;
        int t = threadIdx.x;
        __shared__ unsigned char flag[NN];
        flag[t] = (adj[row * NN + t] != 0.0f) ? 1 : 0;
        __syncthreads();
        unsigned bal = __ballot_sync(0xffffffffu, flag[t] != 0);
        if ((t & 31) == 0) g_mask[row * 3 + (t >> 5)] = bal;
        if (t == 0) {
            int c = 0;
            for (int b = 0; b < NN; b++)
                if (flag[b]) g_nbr[row * NN + c++] = (unsigned char)b;
            for (; c < NN; c++) g_nbr[row * NN + c] = 96;  // pad -> zero row
        }
    }
}

// One block per U: P0[U][m] = sum_{b in Nbar(m) ∩ [0,U)} s0_b * x_b, for m < U.
__global__ void __launch_bounds__(TPB) setup_p0_kernel() {
    int U = blockIdx.x;
    __shared__ float yb[(NN + 1) * DD];   // s0_b * x_b for b<U, zero for rows >= U and row 96
    __shared__ float sS[NN];
    __shared__ unsigned sMask[NN * 3];
    int tid = threadIdx.x;
    int ln = tid & 15, hw = tid >> 4;

    for (int q = tid; q < NN * 3; q += TPB) sMask[q] = g_mask[q];
    __syncthreads();
    if (tid < NN) {
        int deg = 1 + __popc(sMask[tid * 3] & wmask(U, 0))
                    + __popc(sMask[tid * 3 + 1] & wmask(U, 1))
                    + __popc(sMask[tid * 3 + 2] & wmask(U, 2));
        sS[tid] = rsqrtf((float)deg);
    }
    __syncthreads();
    const float4* x04 = (const float4*)g_X0;
    for (int q = tid; q < (NN + 1) * 16; q += TPB) {
        int row = q >> 4;
        float4 v = make_float4(0.f, 0.f, 0.f, 0.f);
        if (row < U) {
            v = x04[q];
            float s = sS[row];
            v.x *= s; v.y *= s; v.z *= s; v.w *= s;
        }
        ((float4*)yb)[q] = v;
    }
    __syncthreads();

    const float4* yb4 = (const float4*)yb;
    float4* p04 = (float4*)g_P0;
    for (int m = hw; m < U; m += 16) {
        int cnt = __popc(sMask[m * 3] & wmask(U, 0))
                + __popc(sMask[m * 3 + 1] & wmask(U, 1))
                + __popc(sMask[m * 3 + 2] & wmask(U, 2));
        float4 a = yb4[m * 16 + ln];   // self term
        const unsigned char* lst = &g_nbr[m * NN];
        int c4 = (cnt + 3) & ~3;
        for (int q = 0; q < c4; q += 4) {
            unsigned pk = *(const unsigned*)(lst + q);   // entries >= cnt hit zero rows
            float4 y0 = yb4[((pk & 255u) << 4) + ln];
            a.x += y0.x; a.y += y0.y; a.z += y0.z; a.w += y0.w;
            float4 y1 = yb4[(((pk >> 8) & 255u) << 4) + ln];
            a.x += y1.x; a.y += y1.y; a.z += y1.z; a.w += y1.w;
            float4 y2 = yb4[(((pk >> 16) & 255u) << 4) + ln];
            a.x += y2.x; a.y += y2.y; a.z += y2.z; a.w += y2.w;
            float4 y3 = yb4[((pk >> 24) << 4) + ln];
            a.x += y3.x; a.y += y3.y; a.z += y3.z; a.w += y3.w;
        }
        p04[(U * NN + m) * 16 + ln] = a;
    }
}

__global__ void __launch_bounds__(TPB) pair_kernel(const float* __restrict__ W1,
                                                   const float* __restrict__ W2,
                                                   float* __restrict__ out) {
    __shared__ float sX[NN * DD];       // x rows, staged only for b in D (b-indexed)
    __shared__ float sS0[NN], sS1d[NN]; // s0, s1-s0
    __shared__ float sG1[NN], sG2[NN];
    __shared__ unsigned sMask[NN * 3];
    __shared__ unsigned char sT[NN];
    __shared__ int sNT;

    // triangular decode, reversed so heavy CTAs launch first
    int t = (NPAIRS - 1) - (int)blockIdx.x;
    int U = (int)((sqrtf(8.0f * (float)t + 1.0f) - 1.0f) * 0.5f);
    while ((U + 1) * (U + 2) / 2 <= t) ++U;
    while (U * (U + 1) / 2 > t) --U;
    int L = t - U * (U + 1) / 2;

    int tid = threadIdx.x;
    int ln = tid & 15, hw = tid >> 4;

    for (int q = tid; q < NN * 3; q += TPB) sMask[q] = g_mask[q];
    if (tid == 0) sNT = 0;
    __syncthreads();

    unsigned Dw0 = sMask[U * 3 + 0] & wmask(L, 0);
    unsigned Dw1 = sMask[U * 3 + 1] & wmask(L, 1);
    unsigned Dw2 = sMask[U * 3 + 2] & wmask(L, 2);
    int nD = __popc(Dw0) + __popc(Dw1) + __popc(Dw2);
    float sU = rsqrtf(1.0f + (float)nD);

    if (tid < NN) {
        int m = tid;
        int deg = 1 + __popc(sMask[m * 3] & wmask(U, 0))
                    + __popc(sMask[m * 3 + 1] & wmask(U, 1))
                    + __popc(sMask[m * 3 + 2] & wmask(U, 2));
        float a = rsqrtf((float)deg);
        sS0[m] = a;
        sS1d[m] = rsqrtf((float)(deg + 1)) - a;
        // T membership: (Nbar(L) ∩ [0,U)) ∪ D ∪ {U}
        int w = m >> 5;
        unsigned bit = 1u << (m & 31);
        unsigned c1 = (sMask[L * 3 + w] | ((m == L) ? bit : 0u)) & wmask(U, w);
        unsigned c2 = (w == 0) ? Dw0 : ((w == 1) ? Dw1 : Dw2);
        unsigned c3 = (m == U) ? bit : 0u;
        if ((c1 | c2 | c3) & bit) {
            int idx = atomicAdd(&sNT, 1);
            sT[idx] = (unsigned char)m;
        }
    }

    // stage x rows for b in D (D = sorted prefix of nbr[U] of length nD)
    for (int q = hw; q < nD; q += 16) {
        int b = g_nbr[U * NN + q];
        ((float4*)sX)[b * 16 + ln] = ((const float4*)g_X0)[b * 16 + ln];
    }

    // per-lane constants
    const float4* W14 = (const float4*)W1;
    float4 w2v = ((const float4*)W2)[ln];
    float4 paV = W14[64 * 16 + ln];           // w64 slice
    float4 pbV = W14[65 * 16 + ln];           // w65 slice
    float4 dv = make_float4(pbV.x - paV.x, pbV.y - paV.y, pbV.z - paV.z, pbV.w - paV.w);
    float4 syU = ((const float4*)g_X0)[U * 16 + ln];
    syU.x += pbV.x; syU.y += pbV.y; syU.z += pbV.z; syU.w += pbV.w;
    if (L == U) { syU.x += paV.x; syU.y += paV.y; syU.z += paV.z; syU.w += paV.w; }
    __syncthreads();

    int nT = sNT;
    float sL0 = sS0[L];
    int rounds = (nT + 15) >> 4;
    const float4* p04 = (const float4*)g_P0;

    for (int r = 0; r < rounds; r++) {
        int idx = r * 16 + hw;
        bool act = (idx < nT);
        int m = sT[act ? idx : 0];
        bool isU = (m == U);

        float4 P = make_float4(0.f, 0.f, 0.f, 0.f);
        if (!isU) P = p04[(U * NN + m) * 16 + ln];

        // scale-bump corrections: b in Nbar(m) ∩ D (weight s1-s0), or b in D (weight s1) if m==U
#pragma unroll
        for (int w = 0; w < 3; w++) {
            unsigned cm = sMask[m * 3 + w];
            if ((m >> 5) == w) cm |= 1u << (m & 31);
            cm &= (w == 0) ? Dw0 : ((w == 1) ? Dw1 : Dw2);
            while (cm) {
                int b = __ffs(cm) - 1;
                cm &= cm - 1;
                b += w << 5;
                float wt = sS1d[b] + (isU ? sS0[b] : 0.f);
                float4 xb = ((const float4*)sX)[b * 16 + ln];
                P.x += wt * xb.x; P.y += wt * xb.y; P.z += wt * xb.z; P.w += wt * xb.w;
            }
        }

        bool inD  = !isU && (m < L) && ((sMask[U * 3 + (m >> 5)] >> (m & 31)) & 1);
        bool inNL = (m == L) || ((sMask[L * 3 + (m >> 5)] >> (m & 31)) & 1);

        if (L != U && !isU && inNL) {   // w64 perturbation at node L (s_L = s0_L)
            P.x += sL0 * paV.x; P.y += sL0 * paV.y; P.z += sL0 * paV.z; P.w += sL0 * paV.w;
        }
        if (isU || inD) {               // U-term s_U * y_U
            P.x += sU * syU.x; P.y += sU * syU.y; P.z += sU * syU.z; P.w += sU * syU.w;
        }

        float sm = isU ? sU : (inD ? (sS0[m] + sS1d[m]) : sS0[m]);
        float c;
        if (L == U) c = 0.f;
        else if (isU) c = -sU;
        else c = (inNL ? sL0 : 0.f) - (inD ? sU : 0.f);

        float g1 = fmaxf(sm * P.x, 0.f) * w2v.x + fmaxf(sm * P.y, 0.f) * w2v.y
                 + fmaxf(sm * P.z, 0.f) * w2v.z + fmaxf(sm * P.w, 0.f) * w2v.w;
        float g2 = fmaxf(sm * (P.x + c * dv.x), 0.f) * w2v.x
                 + fmaxf(sm * (P.y + c * dv.y), 0.f) * w2v.y
                 + fmaxf(sm * (P.z + c * dv.z), 0.f) * w2v.z
                 + fmaxf(sm * (P.w + c * dv.w), 0.f) * w2v.w;
#pragma unroll
        for (int off = 1; off < 16; off <<= 1) {
            g1 += __shfl_xor_sync(0xffffffffu, g1, off);
            g2 += __shfl_xor_sync(0xffffffffu, g2, off);
        }
        if (act && ln == 0) { sG1[m] = sm * g1; sG2[m] = sm * g2; }
    }
    __syncthreads();

    // second conv layer at nodes L and U; out = h2[i] + h2[j]
    int lane = tid & 31, warp = tid >> 5;
    if (warp < 2) {
        const float* G = warp ? sG2 : sG1;
        float res = 0.f;
#pragma unroll
        for (int e = 0; e < 2; e++) {
            int k = e ? U : L;
            int lim = (k == U) ? L : U;
            unsigned w0 = sMask[k * 3 + 0] & wmask(lim, 0);
            unsigned w1 = sMask[k * 3 + 1] & wmask(lim, 1);
            unsigned w2 = sMask[k * 3 + 2] & wmask(lim, 2);
            float v = 0.f;
            if ((w0 >> lane) & 1) v += G[lane];
            if ((w1 >> lane) & 1) v += G[32 + lane];
            if ((w2 >> lane) & 1) v += G[64 + lane];
#pragma unroll
            for (int off = 16; off; off >>= 1) v += __shfl_xor_sync(0xffffffffu, v, off);
            v += G[k];  // self loop
            float sk = (k == U) ? sU : sS0[k];
            res += sk * v;
        }
        if (lane == 0) out[warp ? (U * NN + L) : (L * NN + U)] = res;
    }
}

extern "C" void kernel_launch(void* const* d_in, const int* in_sizes, int n_in,
                              void* d_out, int out_size) {
    const float* z   = (const float*)d_in[0];
    const float* adj = (const float*)d_in[1];
    const float* W1  = (const float*)d_in[2];
    const float* W2  = (const float*)d_in[3];
    float* out = (float*)d_out;

    setup_kernel<<<2 * NN, NN>>>(z, W1, adj);
    setup_p0_kernel<<<NN, TPB>>>();
    pair_kernel<<<NPAIRS, TPB>>>(W1, W2, out);
}

// round 6
// speedup vs baseline: 4.2200x; 1.1644x over previous
#include <cuda_runtime.h>
#include <cstdint>

#define NN 96
#define DD 64
#define TPB 256
#define NCHUNK 624   // sum over U of ceil((U+1)/8)

// Scratch (allocation-free rule): device globals, recomputed deterministically every launch.
__device__ float g_X0[NN * DD];                        // z @ W1[:64]
__device__ float g_P0[NN * NN * DD];                   // [U][m][64]: base pre-activations
__device__ unsigned g_mask[NN * 3];                    // adjacency bitmask rows
__device__ __align__(16) unsigned char g_nbr[NN * NN]; // sorted neighbor lists

// bits [0, n) of 32-bit word w
__device__ __forceinline__ unsigned wmask(int n, int w) {
    int m = n - (w << 5);
    if (m <= 0) return 0u;
    if (m >= 32) return 0xffffffffu;
    return (1u << m) - 1u;
}

// cumulative chunk count before U: U=8a+r -> (a+1)(4a+r)
__device__ __forceinline__ int cumc(int U) {
    int a = U >> 3, r = U & 7;
    return (a + 1) * (4 * a + r);
}

// blocks 0..95: X0 row; blocks 96..191: adjacency row (parallel compaction)
__global__ void setup_kernel(const float* __restrict__ z, const float* __restrict__ W1,
                             const float* __restrict__ adj) {
    if (blockIdx.x < NN) {
        int row = blockIdx.x, c = threadIdx.x;
        __shared__ float zr[DD];
        if (c < DD) zr[c] = z[row * DD + c];
        __syncthreads();
        if (c < DD) {
            float acc = 0.f;
#pragma unroll
            for (int k = 0; k < DD; k++) acc += zr[k] * W1[k * DD + c];
            g_X0[row * DD + c] = acc;
        }
    } else {
        int row = blockIdx.x - NN;
        int t = threadIdx.x;
        __shared__ unsigned smk[3];
        __shared__ unsigned char snb[NN];
        bool f = (adj[row * NN + t] != 0.0f);
        unsigned bal = __ballot_sync(0xffffffffu, f);
        if ((t & 31) == 0) { smk[t >> 5] = bal; g_mask[row * 3 + (t >> 5)] = bal; }
        snb[t] = 96;
        __syncthreads();
        unsigned m0 = smk[0], m1 = smk[1], m2 = smk[2];
        int w = t >> 5, l = t & 31;
        unsigned lm = (1u << l) - 1u;
        unsigned mw = (w == 0) ? m0 : ((w == 1) ? m1 : m2);
        int off = ((w > 0) ? __popc(m0) : 0) + ((w > 1) ? __popc(m1) : 0) + __popc(mw & lm);
        if (f) snb[off] = (unsigned char)t;
        __syncthreads();
        g_nbr[row * NN + t] = snb[t];
    }
}

// 2 blocks per U: P0[U][m] = sum_{b in Nbar(m) ∩ [0,U)} s0_b * x_b, for m < U.
__global__ void __launch_bounds__(TPB) setup_p0_kernel() {
    int U = blockIdx.x >> 1;
    int half = blockIdx.x & 1;
    __shared__ float yb[(NN + 1) * DD];   // s0_b * x_b for b<U, zero rows >= U and 96
    __shared__ float sS[NN];
    __shared__ unsigned sMask[NN * 3];
    int tid = threadIdx.x;
    int ln = tid & 15, hw = tid >> 4;

    for (int q = tid; q < NN * 3; q += TPB) sMask[q] = g_mask[q];
    __syncthreads();
    if (tid < NN) {
        int deg = 1 + __popc(sMask[tid * 3] & wmask(U, 0))
                    + __popc(sMask[tid * 3 + 1] & wmask(U, 1))
                    + __popc(sMask[tid * 3 + 2] & wmask(U, 2));
        sS[tid] = rsqrtf((float)deg);
    }
    __syncthreads();
    const float4* x04 = (const float4*)g_X0;
    for (int q = tid; q < (NN + 1) * 16; q += TPB) {
        int row = q >> 4;
        float4 v = make_float4(0.f, 0.f, 0.f, 0.f);
        if (row < U) {
            v = x04[q];
            float s = sS[row];
            v.x *= s; v.y *= s; v.z *= s; v.w *= s;
        }
        ((float4*)yb)[q] = v;
    }
    __syncthreads();

    const float4* yb4 = (const float4*)yb;
    float4* p04 = (float4*)g_P0;
    for (int m = hw + (half << 4); m < U; m += 32) {
        int cnt = __popc(sMask[m * 3] & wmask(U, 0))
                + __popc(sMask[m * 3 + 1] & wmask(U, 1))
                + __popc(sMask[m * 3 + 2] & wmask(U, 2));
        float4 a = yb4[m * 16 + ln];   // self term
        const unsigned char* lst = &g_nbr[m * NN];
        int c4 = (cnt + 3) & ~3;
        for (int q = 0; q < c4; q += 4) {
            unsigned pk = *(const unsigned*)(lst + q);   // entries >= cnt hit zero rows
            float4 y0 = yb4[((pk & 255u) << 4) + ln];
            a.x += y0.x; a.y += y0.y; a.z += y0.z; a.w += y0.w;
            float4 y1 = yb4[(((pk >> 8) & 255u) << 4) + ln];
            a.x += y1.x; a.y += y1.y; a.z += y1.z; a.w += y1.w;
            float4 y2 = yb4[(((pk >> 16) & 255u) << 4) + ln];
            a.x += y2.x; a.y += y2.y; a.z += y2.z; a.w += y2.w;
            float4 y3 = yb4[((pk >> 24) << 4) + ln];
            a.x += y3.x; a.y += y3.y; a.z += y3.z; a.w += y3.w;
        }
        p04[(U * NN + m) * 16 + ln] = a;
    }
}

// One CTA per (U, 8-L chunk); one warp per pair (L,U). Layer 2 fused inline.
__global__ void __launch_bounds__(TPB) pair_kernel(const float* __restrict__ W1,
                                                   const float* __restrict__ W2,
                                                   float* __restrict__ out) {
    __shared__ unsigned sMask[NN * 3];
    __shared__ float sS0[NN], sS1d[NN];
    __shared__ float sX[NN * DD];            // x rows staged for b in N(U)∩[0,U), b-indexed
    __shared__ unsigned char sTl[8][NN];     // per-warp target list

    // block -> (U, Lbase); reversed so heavy chunks first
    int b = (NCHUNK - 1) - (int)blockIdx.x;
    int a0 = (int)(sqrtf((float)b) * 0.5f);
    int U = 8 * a0;
    if (U > 95) U = 95;
    while (U < 95 && cumc(U + 1) <= b) ++U;
    while (U > 0 && cumc(U) > b) --U;
    int Lbase = (b - cumc(U)) * 8;

    int tid = threadIdx.x;
    int lane = tid & 31, warp = tid >> 5;

    for (int q = tid; q < NN * 3; q += TPB) sMask[q] = g_mask[q];
    __syncthreads();

    unsigned uw0 = sMask[U * 3 + 0] & wmask(U, 0);
    unsigned uw1 = sMask[U * 3 + 1] & wmask(U, 1);
    unsigned uw2 = sMask[U * 3 + 2] & wmask(U, 2);
    int cntU = __popc(uw0) + __popc(uw1) + __popc(uw2);

    if (tid < NN) {
        int m = tid;
        int deg = 1 + __popc(sMask[m * 3] & wmask(U, 0))
                    + __popc(sMask[m * 3 + 1] & wmask(U, 1))
                    + __popc(sMask[m * 3 + 2] & wmask(U, 2));
        float s0 = rsqrtf((float)deg);
        sS0[m] = s0;
        sS1d[m] = rsqrtf((float)(deg + 1)) - s0;
    }
    // stage x rows for b in N(U)∩[0,U)  (covers every warp's D set)
    const float4* x04 = (const float4*)g_X0;
    for (int q = tid >> 4; q < cntU; q += 16) {
        int bb = g_nbr[U * NN + q];
        ((float4*)sX)[bb * 16 + (tid & 15)] = x04[bb * 16 + (tid & 15)];
    }
    __syncthreads();

    int L = Lbase + warp;
    if (L > U) return;

    // ---- per-warp pair (L, U) ----
    unsigned Dw0 = sMask[U * 3 + 0] & wmask(L, 0);
    unsigned Dw1 = sMask[U * 3 + 1] & wmask(L, 1);
    unsigned Dw2 = sMask[U * 3 + 2] & wmask(L, 2);
    int nD = __popc(Dw0) + __popc(Dw1) + __popc(Dw2);
    float sU = rsqrtf(1.0f + (float)nD);
    float sL0 = sS0[L];

    // target words: (Nbar(L)∩[0,U)) ∪ D ∪ {U}
    unsigned t0 = ((sMask[L * 3 + 0] | ((L < 32) ? (1u << L) : 0u)) & wmask(U, 0)) | Dw0;
    unsigned t1 = ((sMask[L * 3 + 1] | ((L >= 32 && L < 64) ? (1u << (L & 31)) : 0u)) & wmask(U, 1)) | Dw1;
    unsigned t2 = ((sMask[L * 3 + 2] | ((L >= 64) ? (1u << (L & 31)) : 0u)) & wmask(U, 2)) | Dw2;
    if (U < 32) t0 |= 1u << U; else if (U < 64) t1 |= 1u << (U & 31); else t2 |= 1u << (U & 31);

    // ballot-free compaction (t words uniform across warp)
    unsigned lm = (1u << lane) - 1u;
    int c0 = __popc(t0), c1 = __popc(t1);
    if ((t0 >> lane) & 1) sTl[warp][__popc(t0 & lm)] = (unsigned char)lane;
    if ((t1 >> lane) & 1) sTl[warp][c0 + __popc(t1 & lm)] = (unsigned char)(32 + lane);
    if ((t2 >> lane) & 1) sTl[warp][c0 + c1 + __popc(t2 & lm)] = (unsigned char)(64 + lane);
    int nT = c0 + c1 + __popc(t2);
    __syncwarp();

    // per-lane constants (float4 slice ln)
    int ln = lane & 15, h = lane >> 4;
    const float4* W14 = (const float4*)W1;
    float4 w2v = __ldg(&((const float4*)W2)[ln]);
    float4 paV = __ldg(&W14[64 * 16 + ln]);
    float4 pbV = __ldg(&W14[65 * 16 + ln]);
    float4 dv = make_float4(pbV.x - paV.x, pbV.y - paV.y, pbV.z - paV.z, pbV.w - paV.w);
    float4 yU = __ldg(&x04[U * 16 + ln]);
    yU.x += pbV.x; yU.y += pbV.y; yU.z += pbV.z; yU.w += pbV.w;
    if (L == U) { yU.x += paV.x; yU.y += paV.y; yU.z += paV.z; yU.w += paV.w; }

    const float4* p04 = (const float4*)g_P0;
    float acc1 = 0.f, acc2 = 0.f;
    int rounds = (nT + 1) >> 1;

    for (int r = 0; r < rounds; r++) {
        int idx = 2 * r + h;
        bool act = (idx < nT);
        int m = sTl[warp][act ? idx : 0];
        bool isU = (m == U);

        float4 P = make_float4(0.f, 0.f, 0.f, 0.f);
        if (!isU) P = __ldg(&p04[(U * NN + m) * 16 + ln]);

        // scale-bump corrections over b in Nbar(m) ∩ D (s1-s0), +s0 if m==U (full s1 weight)
        int mw = m >> 5;
        unsigned mb = 1u << (m & 31);
#pragma unroll
        for (int w = 0; w < 3; w++) {
            unsigned cm = sMask[m * 3 + w] | ((mw == w) ? mb : 0u);
            cm &= (w == 0) ? Dw0 : ((w == 1) ? Dw1 : Dw2);
            while (cm) {
                int bb = __ffs(cm) - 1;
                cm &= cm - 1;
                bb += w << 5;
                float wt = sS1d[bb] + (isU ? sS0[bb] : 0.f);
                float4 xb = ((const float4*)sX)[bb * 16 + ln];
                P.x += wt * xb.x; P.y += wt * xb.y; P.z += wt * xb.z; P.w += wt * xb.w;
            }
        }

        unsigned dwm = (mw == 0) ? Dw0 : ((mw == 1) ? Dw1 : Dw2);
        bool inD  = !isU && ((dwm & mb) != 0);
        bool inNL = (m == L) || ((sMask[L * 3 + mw] & mb) != 0);

        if (L != U && !isU && inNL) {   // node L's w64 perturbation (scale s0_L)
            P.x += sL0 * paV.x; P.y += sL0 * paV.y; P.z += sL0 * paV.z; P.w += sL0 * paV.w;
        }
        if (isU || inD) {               // U term: s_U * y_U
            P.x += sU * yU.x; P.y += sU * yU.y; P.z += sU * yU.z; P.w += sU * yU.w;
        }

        float sm = isU ? sU : (sS0[m] + (inD ? sS1d[m] : 0.f));
        float c = (L == U) ? 0.f : (isU ? -sU : ((inNL ? sL0 : 0.f) - (inD ? sU : 0.f)));

        float g1 = fmaxf(sm * P.x, 0.f) * w2v.x + fmaxf(sm * P.y, 0.f) * w2v.y
                 + fmaxf(sm * P.z, 0.f) * w2v.z + fmaxf(sm * P.w, 0.f) * w2v.w;
        float g2 = fmaxf(sm * (P.x + c * dv.x), 0.f) * w2v.x
                 + fmaxf(sm * (P.y + c * dv.y), 0.f) * w2v.y
                 + fmaxf(sm * (P.z + c * dv.z), 0.f) * w2v.z
                 + fmaxf(sm * (P.w + c * dv.w), 0.f) * w2v.w;
#pragma unroll
        for (int off = 1; off < 16; off <<= 1) {
            g1 += __shfl_xor_sync(0xffffffffu, g1, off);
            g2 += __shfl_xor_sync(0xffffffffu, g2, off);
        }

        // fused layer 2: coef = s_L*pa[L,m] + s_U*pa[U,m]
        float coef = 0.f;
        if (act) {
            if (isU) coef = (L == U) ? 2.f * sU : sU;
            else     coef = (inNL ? sL0 : 0.f) + (inD ? sU : 0.f);
        }
        coef *= sm;
        acc1 += coef * g1;
        acc2 += coef * g2;
    }

    acc1 += __shfl_xor_sync(0xffffffffu, acc1, 16);
    acc2 += __shfl_xor_sync(0xffffffffu, acc2, 16);
    if (lane == 0) {
        out[L * NN + U] = acc1;
        out[U * NN + L] = acc2;
    }
}

extern "C" void kernel_launch(void* const* d_in, const int* in_sizes, int n_in,
                              void* d_out, int out_size) {
    const float* z   = (const float*)d_in[0];
    const float* adj = (const float*)d_in[1];
    const float* W1  = (const float*)d_in[2];
    const float* W2  = (const float*)d_in[3];
    float* out = (float*)d_out;

    setup_kernel<<<2 * NN, NN>>>(z, W1, adj);
    setup_p0_kernel<<<2 * NN, TPB>>>();
    pair_kernel<<<NCHUNK, TPB>>>(W1, W2, out);
}